// round 13
// baseline (speedup 1.0000x reference)
#include <cuda_runtime.h>
#include <cstdint>

#define NMAX 50000
#define EMAX 800000
#define RR 3
#define GGR 64
#define PCH 8
#define SCB 1024
#define NTILES 13

// ---------------- scratch (device globals; no allocation) ----------------
__device__ float g_xr   [RR*NMAX*64];
__device__ float g_beta [RR*NMAX*64];
__device__ float g_gamma[RR*NMAX*64];
__device__ float g_xs   [NMAX*64];
__device__ float g_fsb  [NMAX*64];
__device__ float g_fsg  [NMAX*64];
__device__ float g_xp   [NMAX*64];
__device__ float g_asrc [NMAX];
__device__ float g_adst [NMAX];
__device__ int      g_cnt[RR*NMAX];
__device__ int      g_pos[RR*NMAX];
__device__ int      g_off[RR*NMAX+1];
__device__ int      g_bsum[256];
__device__ int      g_bofs[256];
__device__ int      g_rec[EMAX];
__device__ float g_feats[NMAX*128];
__device__ float g_ppmax[GGR*PCH*128];
__device__ float g_ppsum[GGR*PCH*128];
__device__ float g_pmax [GGR*128];
__device__ float g_pmean[GGR*128];
__device__ float g_hidden[GGR*64];

// ---------------- helpers ----------------
__device__ __forceinline__ uint64_t pack2(float a, float b){
    uint64_t r; asm("mov.b64 %0,{%1,%2};" : "=l"(r) : "f"(a), "f"(b)); return r;
}
__device__ __forceinline__ void fma2(uint64_t &d, uint64_t a, uint64_t b){
    asm("fma.rn.f32x2 %0,%1,%2,%0;" : "+l"(d) : "l"(a), "l"(b));
}

// ---------------- init: zero CSR counters ----------------
__global__ void kzero(int m){
    int i = blockIdx.x*blockDim.x + threadIdx.x;
    if (i < m){ g_cnt[i] = 0; g_pos[i] = 0; }
}

// ---------------- K1: fused node-dense GEMMs, double-buffered ----------------
// 256 threads, 128 nodes/block; thread (half,nl) computes cols [half*32, half*32+32)
__global__ __launch_bounds__(256, 3) void k1(
    const float* __restrict__ x,
    const float* __restrict__ flW, const float* __restrict__ ffW, const float* __restrict__ ffb,
    const float* __restrict__ skW, const float* __restrict__ sfW, const float* __restrict__ sfb,
    const float* __restrict__ gatW,
    const float* __restrict__ atS, const float* __restrict__ atD, int n)
{
    extern __shared__ float sm[];
    float* Xs   = sm;            // 64*128 = 8192 floats
    float* Wbuf = sm + 8192;     // 2 * 4096 floats
    float* sdot = sm + 16384;    // 512 floats

    int tid  = threadIdx.x;
    int half = tid >> 7;
    int nl   = tid & 127;
    int node = blockIdx.x*128 + nl;
    int nc   = node < n ? node : n-1;

    // stage x: thread loads 32 floats (its half of its node's row), transposed
    {
        const float4* xp4 = (const float4*)(x + (size_t)nc*64) + half*8;
        #pragma unroll
        for (int q = 0; q < 8; q++){
            float4 v = xp4[q];
            int d = half*32 + q*4;
            Xs[(d+0)*128 + nl] = v.x;
            Xs[(d+1)*128 + nl] = v.y;
            Xs[(d+2)*128 + nl] = v.z;
            Xs[(d+3)*128 + nl] = v.w;
        }
    }

    // tile descriptors
    const float* wsrc[NTILES]; int ldwA[NTILES], jofA[NTILES];
    const float* bA[NTILES]; float* oA[NTILES];
    wsrc[0]=skW;  ldwA[0]=64;  jofA[0]=0;  bA[0]=nullptr; oA[0]=g_xs;
    wsrc[1]=sfW;  ldwA[1]=128; jofA[1]=0;  bA[1]=sfb;     oA[1]=g_fsb;
    wsrc[2]=sfW;  ldwA[2]=128; jofA[2]=64; bA[2]=sfb;     oA[2]=g_fsg;
    #pragma unroll
    for (int r = 0; r < RR; r++){
        wsrc[3+3*r]=flW + (size_t)r*64*64;  ldwA[3+3*r]=64;  jofA[3+3*r]=0;  bA[3+3*r]=nullptr;    oA[3+3*r]=g_xr  + (size_t)r*n*64;
        wsrc[4+3*r]=ffW + (size_t)r*64*128; ldwA[4+3*r]=128; jofA[4+3*r]=0;  bA[4+3*r]=ffb+r*128;  oA[4+3*r]=g_beta+ (size_t)r*n*64;
        wsrc[5+3*r]=ffW + (size_t)r*64*128; ldwA[5+3*r]=128; jofA[5+3*r]=64; bA[5+3*r]=ffb+r*128;  oA[5+3*r]=g_gamma+(size_t)r*n*64;
    }
    wsrc[12]=gatW; ldwA[12]=64; jofA[12]=0; bA[12]=nullptr; oA[12]=g_xp;

    // per-thread weight fragment: 16 consecutive floats of the 64x64 tile
    int wrow = tid >> 2;            // k = tid*16; row = k/64
    int wcol = (tid & 3) * 16;
    float4 p0, p1, p2, p3;

    // prefetch tile 0
    {
        const float* base = wsrc[0] + (size_t)wrow*ldwA[0] + jofA[0] + wcol;
        p0 = *(const float4*)(base);
        p1 = *(const float4*)(base + 4);
        p2 = *(const float4*)(base + 8);
        p3 = *(const float4*)(base + 12);
    }

    for (int t = 0; t < NTILES; t++){
        float* Wb = Wbuf + (t & 1)*4096;
        // commit prefetched tile to smem
        float4* wb4 = (float4*)(Wb + tid*16);
        wb4[0] = p0; wb4[1] = p1; wb4[2] = p2; wb4[3] = p3;
        __syncthreads();
        // prefetch next tile from gmem (latency hidden by compute below)
        if (t < NTILES-1){
            const float* base = wsrc[t+1] + (size_t)wrow*ldwA[t+1] + jofA[t+1] + wcol;
            p0 = *(const float4*)(base);
            p1 = *(const float4*)(base + 4);
            p2 = *(const float4*)(base + 8);
            p3 = *(const float4*)(base + 12);
        }

        // compute: 32 output cols per thread
        uint64_t acc[16];
        {
            const float* bias = bA[t];
            if (bias){
                int c0 = jofA[t] + half*32;
                #pragma unroll
                for (int j = 0; j < 16; j++)
                    acc[j] = pack2(__ldg(bias + c0 + 2*j), __ldg(bias + c0 + 2*j + 1));
            } else {
                #pragma unroll
                for (int j = 0; j < 16; j++) acc[j] = 0ull;
            }
        }
        const float* wbase = Wb + half*32;
        for (int d = 0; d < 64; d++){
            float xv = Xs[d*128 + nl];
            uint64_t x2 = pack2(xv, xv);
            const ulonglong2* wr = (const ulonglong2*)(wbase + d*64);
            #pragma unroll
            for (int j = 0; j < 8; j++){
                ulonglong2 w = wr[j];
                fma2(acc[2*j],   x2, w.x);
                fma2(acc[2*j+1], x2, w.y);
            }
        }
        if (node < n){
            ulonglong2* o = (ulonglong2*)(oA[t] + (size_t)node*64 + half*32);
            #pragma unroll
            for (int j = 0; j < 8; j++) o[j] = make_ulonglong2(acc[2*j], acc[2*j+1]);
        }

        if (t == NTILES-1){
            // attention dots: partial over this thread's 32 cols, reduce across halves
            float a = 0.f, b = 0.f;
            int c0 = half*32;
            #pragma unroll
            for (int j = 0; j < 16; j++){
                float lo = __uint_as_float((unsigned)acc[j]);
                float hi = __uint_as_float((unsigned)(acc[j] >> 32));
                a = fmaf(lo, __ldg(atS + c0 + 2*j), a); a = fmaf(hi, __ldg(atS + c0 + 2*j + 1), a);
                b = fmaf(lo, __ldg(atD + c0 + 2*j), b); b = fmaf(hi, __ldg(atD + c0 + 2*j + 1), b);
            }
            sdot[(half*128 + nl)*2    ] = a;
            sdot[(half*128 + nl)*2 + 1] = b;
            __syncthreads();
            if (half == 0 && node < n){
                g_asrc[node] = sdot[nl*2]     + sdot[(128+nl)*2];
                g_adst[node] = sdot[nl*2 + 1] + sdot[(128+nl)*2 + 1];
            }
        }
    }
}

// ---------------- CSR build over (dst*3 + type) keys ----------------
__global__ void khist(const int* __restrict__ dst, const int* __restrict__ et, int E){
    int i = blockIdx.x*blockDim.x + threadIdx.x;
    if (i < E) atomicAdd(&g_cnt[dst[i]*RR + et[i]], 1);
}

__global__ __launch_bounds__(SCB) void kscanA(int m){
    __shared__ int wsum[32];
    int i = blockIdx.x*SCB + threadIdx.x;
    int lane = threadIdx.x & 31, wid = threadIdx.x >> 5;
    int v = (i < m) ? g_cnt[i] : 0;
    int inc = v;
    #pragma unroll
    for (int o = 1; o < 32; o <<= 1){
        int u = __shfl_up_sync(0xffffffffu, inc, o);
        if (lane >= o) inc += u;
    }
    if (lane == 31) wsum[wid] = inc;
    __syncthreads();
    if (wid == 0){
        int s = wsum[lane];
        int t = s;
        #pragma unroll
        for (int o = 1; o < 32; o <<= 1){
            int u = __shfl_up_sync(0xffffffffu, t, o);
            if (lane >= o) t += u;
        }
        wsum[lane] = t - s;
    }
    __syncthreads();
    int excl = inc - v + wsum[wid];
    if (i < m) g_off[i] = excl;
    if (threadIdx.x == SCB-1) g_bsum[blockIdx.x] = excl + v;
}

__global__ void kscanB(int nb){
    __shared__ int ss[256];
    int t = threadIdx.x;
    int v = (t < nb) ? g_bsum[t] : 0;
    ss[t] = v; __syncthreads();
    #pragma unroll
    for (int o = 1; o < 256; o <<= 1){
        int u = (t >= o) ? ss[t-o] : 0;
        __syncthreads();
        ss[t] += u;
        __syncthreads();
    }
    if (t < nb) g_bofs[t] = ss[t] - v;
}

__global__ __launch_bounds__(SCB) void kscanC(int m, int E){
    int i = blockIdx.x*SCB + threadIdx.x;
    if (i < m) g_off[i] += g_bofs[blockIdx.x];
    if (blockIdx.x == 0 && threadIdx.x == 0) g_off[m] = E;
}

__global__ void kscatter(const int* __restrict__ src, const int* __restrict__ dst,
                         const int* __restrict__ et, int E){
    int i = blockIdx.x*blockDim.x + threadIdx.x;
    if (i >= E) return;
    int key = dst[i]*RR + et[i];
    int p = g_off[key] + atomicAdd(&g_pos[key], 1);
    g_rec[p] = src[i];
}

// ---------------- fused edge gather: FiLM + GAT, warp per dst ----------------
__global__ void kedge(const float* __restrict__ gatb, int n){
    int w = (blockIdx.x*blockDim.x + threadIdx.x) >> 5;
    int lane = threadIdx.x & 31;
    if (w >= n) return;

    float aD = g_adst[w];
    float es0 = g_asrc[w] + aD;
    float ssum = __expf(fmaxf(es0, 0.2f*es0));
    float2 xpw = ((const float2*)(g_xp + (size_t)w*64))[lane];
    float2 gacc = make_float2(ssum*xpw.x, ssum*xpw.y);

    float aggx = 0.f, aggy = 0.f;
    int base = w*RR;
    #pragma unroll
    for (int t = 0; t < RR; t++){
        int beg = g_off[base+t], end = g_off[base+t+1];
        if (beg == end) continue;
        const float* xrb = g_xr + (size_t)t*n*64;
        float2 gm = ((const float2*)(g_gamma + ((size_t)t*n + w)*64))[lane];
        float2 bt = ((const float2*)(g_beta  + ((size_t)t*n + w)*64))[lane];
        float ax = 0.f, ay = 0.f;
        int s = g_rec[beg];
        for (int e = beg; e < end; e++){
            int sn = (e+1 < end) ? g_rec[e+1] : 0;
            float2 xv = ((const float2*)(xrb  + (size_t)s*64))[lane];
            float2 pv = ((const float2*)(g_xp + (size_t)s*64))[lane];
            float as = g_asrc[s];
            ax += fmaxf(fmaf(gm.x, xv.x, bt.x), 0.f);
            ay += fmaxf(fmaf(gm.y, xv.y, bt.y), 0.f);
            float es = as + aD;
            float al = __expf(fmaxf(es, 0.2f*es));
            gacc.x = fmaf(al, pv.x, gacc.x);
            gacc.y = fmaf(al, pv.y, gacc.y);
            ssum += al;
            s = sn;
        }
        float inv = 1.f / (float)(end - beg);
        aggx = fmaf(ax, inv, aggx);
        aggy = fmaf(ay, inv, aggy);
    }

    size_t o = (size_t)w*64 + lane*2;
    float2 xs = *(const float2*)(g_xs  + o);
    float2 fb = *(const float2*)(g_fsb + o);
    float2 fg = *(const float2*)(g_fsg + o);
    float o1x = fmaxf(fmaxf(fmaf(fg.x, xs.x, fb.x), 0.f) + aggx, 0.f);
    float o1y = fmaxf(fmaxf(fmaf(fg.y, xs.y, fb.y), 0.f) + aggy, 0.f);
    *(float2*)(g_feats + (size_t)w*128 + 2*lane) = make_float2(o1x, o1y);

    float inv = 1.f / ssum;
    float o2x = fmaxf(fmaf(gacc.x, inv, gatb[2*lane  ]), 0.f);
    float o2y = fmaxf(fmaf(gacc.y, inv, gatb[2*lane+1]), 0.f);
    *(float2*)(g_feats + (size_t)w*128 + 64 + 2*lane) = make_float2(o2x, o2y);
}

// ---------------- pooling: (graph, chunk) partials, then reduce ----------------
__global__ void kpool(const int* __restrict__ gb, int n){
    int g = blockIdx.x / PCH, ch = blockIdx.x % PCH;
    int c = threadIdx.x;
    int lo = 0, hi = n;
    while (lo < hi){ int m = (lo+hi)>>1; if (gb[m] < g) lo = m+1; else hi = m; }
    int start = lo; hi = n;
    while (lo < hi){ int m = (lo+hi)>>1; if (gb[m] < g+1) lo = m+1; else hi = m; }
    int end = lo;
    int len = end - start;
    int b = start + (len*ch)/PCH;
    int e = start + (len*(ch+1))/PCH;
    float mx = 0.f, sm = 0.f;
    for (int i = b; i < e; i++){
        float v = g_feats[(size_t)i*128 + c];
        mx = fmaxf(mx, v); sm += v;
    }
    g_ppmax[(g*PCH + ch)*128 + c] = mx;
    g_ppsum[(g*PCH + ch)*128 + c] = sm;
}

__global__ void kpoolred(const int* __restrict__ gb, int n){
    int g = blockIdx.x, c = threadIdx.x;
    int lo = 0, hi = n;
    while (lo < hi){ int m = (lo+hi)>>1; if (gb[m] < g) lo = m+1; else hi = m; }
    int start = lo; hi = n;
    while (lo < hi){ int m = (lo+hi)>>1; if (gb[m] < g+1) lo = m+1; else hi = m; }
    int cnt = lo - start;
    float mx = 0.f, sm = 0.f;
    #pragma unroll
    for (int ch = 0; ch < PCH; ch++){
        mx = fmaxf(mx, g_ppmax[(g*PCH + ch)*128 + c]);
        sm += g_ppsum[(g*PCH + ch)*128 + c];
    }
    g_pmax[g*128 + c]  = mx;
    g_pmean[g*128 + c] = sm / (float)(cnt > 0 ? cnt : 1);
}

// ---------------- MLP hidden ----------------
__global__ void k6a(const float* __restrict__ linW, const float* __restrict__ linb){
    int idx = blockIdx.x*blockDim.x + threadIdx.x;
    if (idx >= GGR*64) return;
    int g = idx >> 6, j = idx & 63;
    float s = linb[j];
    #pragma unroll 4
    for (int k = 0; k < 128; k++) s = fmaf(g_pmax[g*128 + k],  linW[k*64 + j], s);
    #pragma unroll 4
    for (int k = 0; k < 128; k++) s = fmaf(g_pmean[g*128 + k], linW[(128+k)*64 + j], s);
    g_hidden[idx] = fmaxf(s, 0.f);
}

// ---------------- logits + log_softmax ----------------
__global__ void k6b(const float* __restrict__ fcW, const float* __restrict__ fcb,
                    float* __restrict__ out){
    int g = threadIdx.x;
    if (g >= GGR) return;
    float l[10];
    #pragma unroll
    for (int c = 0; c < 10; c++) l[c] = fcb[c];
    for (int j = 0; j < 64; j++){
        float h = g_hidden[g*64 + j];
        #pragma unroll
        for (int c = 0; c < 10; c++) l[c] = fmaf(h, fcW[j*10 + c], l[c]);
    }
    float mx = l[0];
    #pragma unroll
    for (int c = 1; c < 10; c++) mx = fmaxf(mx, l[c]);
    float se = 0.f;
    #pragma unroll
    for (int c = 0; c < 10; c++) se += expf(l[c] - mx);
    float lse = mx + logf(se);
    #pragma unroll
    for (int c = 0; c < 10; c++) out[g*10 + c] = l[c] - lse;
}

// ---------------- launch ----------------
extern "C" void kernel_launch(void* const* d_in, const int* in_sizes, int n_in,
                              void* d_out, int out_size){
    const float* x    = (const float*)d_in[0];
    const int*   ei   = (const int*)  d_in[1];
    const int*   et   = (const int*)  d_in[2];
    const int*   gb   = (const int*)  d_in[3];
    const float* flW  = (const float*)d_in[4];
    const float* ffW  = (const float*)d_in[5];
    const float* ffb  = (const float*)d_in[6];
    const float* skW  = (const float*)d_in[7];
    const float* sfW  = (const float*)d_in[8];
    const float* sfb  = (const float*)d_in[9];
    const float* gatW = (const float*)d_in[10];
    const float* atS  = (const float*)d_in[11];
    const float* atD  = (const float*)d_in[12];
    const float* gatb = (const float*)d_in[13];
    const float* linW = (const float*)d_in[14];
    const float* linb = (const float*)d_in[15];
    const float* fcW  = (const float*)d_in[16];
    const float* fcb  = (const float*)d_in[17];

    int n = in_sizes[0] / 64;
    int E = in_sizes[1] / 2;
    const int* src = ei;
    const int* dst = ei + E;
    int m = n * RR;

    static cudaStream_t s2 = nullptr;
    static cudaEvent_t evFork = nullptr, evJoin = nullptr;
    if (!s2){
        cudaStreamCreateWithFlags(&s2, cudaStreamNonBlocking);
        cudaEventCreateWithFlags(&evFork, cudaEventDisableTiming);
        cudaEventCreateWithFlags(&evJoin, cudaEventDisableTiming);
        cudaFuncSetAttribute(k1, cudaFuncAttributeMaxDynamicSharedMemorySize, 69632);
    }

    int nbScan = (m + SCB-1)/SCB;
    int smemK1 = 16896 * 4;  // Xs 8192 + W 2*4096 + sdot 512 floats

    // fork: CSR build on side stream, dense GEMMs on main stream
    cudaEventRecord(evFork, 0);
    cudaStreamWaitEvent(s2, evFork, 0);

    kzero   <<<(m + 255)/256, 256, 0, s2>>>(m);
    khist   <<<(E + 255)/256, 256, 0, s2>>>(dst, et, E);
    kscanA  <<<nbScan, SCB, 0, s2>>>(m);

    k1<<<(n + 127)/128, 256, smemK1>>>(x, flW, ffW, ffb, skW, sfW, sfb, gatW, atS, atD, n);

    kscanB  <<<1, 256, 0, s2>>>(nbScan);
    kscanC  <<<nbScan, SCB, 0, s2>>>(m, E);
    kscatter<<<(E + 255)/256, 256, 0, s2>>>(src, dst, et, E);
    cudaEventRecord(evJoin, s2);

    cudaStreamWaitEvent(0, evJoin, 0);
    kedge<<<(n + 7)/8, 256>>>(gatb, n);
    kpool<<<GGR*PCH, 128>>>(gb, n);
    kpoolred<<<GGR, 128>>>(gb, n);
    k6a<<<(GGR*64 + 127)/128, 128>>>(linW, linb);
    k6b<<<1, 64>>>(fcW, fcb, (float*)d_out);
}

// round 15
// speedup vs baseline: 1.4789x; 1.4789x over previous
#include <cuda_runtime.h>
#include <cstdint>

#define NMAX 50000
#define EMAX 800000
#define RR 3
#define GGR 64
#define PCH 8
#define SCB 1024

// ---------------- scratch (device globals; no allocation) ----------------
__device__ float g_xr   [RR*NMAX*64];
__device__ float g_beta [RR*NMAX*64];
__device__ float g_gamma[RR*NMAX*64];
__device__ float g_xs   [NMAX*64];
__device__ float g_fsb  [NMAX*64];
__device__ float g_fsg  [NMAX*64];
__device__ float g_xp   [NMAX*64];
__device__ float g_asrc [NMAX];
__device__ float g_adst [NMAX];
__device__ int      g_cnt[RR*NMAX];
__device__ int      g_pos[RR*NMAX];
__device__ int      g_off[RR*NMAX+1];
__device__ int      g_bsum[256];
__device__ int      g_bofs[256];
__device__ int      g_rec[EMAX];
__device__ float g_feats[NMAX*128];
__device__ float g_ppmax[GGR*PCH*128];
__device__ float g_ppsum[GGR*PCH*128];
__device__ float g_pmax [GGR*128];
__device__ float g_pmean[GGR*128];
__device__ float g_hidden[GGR*64];

// ---------------- helpers ----------------
__device__ __forceinline__ uint64_t pack2(float a, float b){
    uint64_t r; asm("mov.b64 %0,{%1,%2};" : "=l"(r) : "f"(a), "f"(b)); return r;
}
__device__ __forceinline__ void fma2(uint64_t &d, uint64_t a, uint64_t b){
    asm("fma.rn.f32x2 %0,%1,%2,%0;" : "+l"(d) : "l"(a), "l"(b));
}

// ---------------- init: zero CSR counters ----------------
__global__ void kzero(int m){
    int i = blockIdx.x*blockDim.x + threadIdx.x;
    if (i < m){ g_cnt[i] = 0; g_pos[i] = 0; }
}

// ---------------- K1: fused node-dense GEMMs ----------------
// 256 threads, 256 nodes/block. Thread (c = tid>>7, m = tid&127) computes
// nodes {2m, 2m+1} x cols [c*32, c*32+32). Per d: 1 LDS.64 + 8 LDS.128 -> 32 FFMA2.
__global__ __launch_bounds__(256, 2) void k1(
    const float* __restrict__ x,
    const float* __restrict__ flW, const float* __restrict__ ffW, const float* __restrict__ ffb,
    const float* __restrict__ skW, const float* __restrict__ sfW, const float* __restrict__ sfb,
    const float* __restrict__ gatW,
    const float* __restrict__ atS, const float* __restrict__ atD, int n)
{
    extern __shared__ float sm[];
    float* Xs   = sm;             // 64*256 = 16384 floats
    float* Wbuf = sm + 16384;     // 2*4096 floats
    float* sdot = sm + 24576;     // 1024 floats

    int tid = threadIdx.x;
    int c   = tid >> 7;      // column half
    int m   = tid & 127;     // node-pair index
    int node0 = blockIdx.x*256 + 2*m;

    // stage x: thread u loads node (blk*256+u), transposed into Xs[d][u]
    {
        int nd = blockIdx.x*256 + tid;
        int nc = nd < n ? nd : n-1;
        const float4* xp4 = (const float4*)(x + (size_t)nc*64);
        #pragma unroll
        for (int q = 0; q < 16; q++){
            float4 v = xp4[q];
            Xs[(4*q+0)*256 + tid] = v.x;
            Xs[(4*q+1)*256 + tid] = v.y;
            Xs[(4*q+2)*256 + tid] = v.z;
            Xs[(4*q+3)*256 + tid] = v.w;
        }
    }

    float4 p0, p1, p2, p3;   // weight prefetch regs

    auto pref = [&](const float* Wg, int ldw, int jof){
        int i0 = tid*4;
        int i1 = i0 + 1024, i2 = i0 + 2048, i3 = i0 + 3072;
        p0 = *(const float4*)(Wg + (size_t)(i0>>6)*ldw + jof + (i0&63));
        p1 = *(const float4*)(Wg + (size_t)(i1>>6)*ldw + jof + (i1&63));
        p2 = *(const float4*)(Wg + (size_t)(i2>>6)*ldw + jof + (i2&63));
        p3 = *(const float4*)(Wg + (size_t)(i3>>6)*ldw + jof + (i3&63));
    };

    auto tile = [&](int t, const float* bias, int bof, float* outArr,
                    const float* WgN, int ldwN, int jofN, bool att){
        float* Wb = Wbuf + (t & 1)*4096;
        *(float4*)(Wb +        tid*4) = p0;
        *(float4*)(Wb + 1024 + tid*4) = p1;
        *(float4*)(Wb + 2048 + tid*4) = p2;
        *(float4*)(Wb + 3072 + tid*4) = p3;
        __syncthreads();
        if (WgN) pref(WgN, ldwN, jofN);   // latency hidden under compute

        uint64_t accA[16], accB[16];
        if (bias){
            int c0 = bof + c*32;
            #pragma unroll
            for (int j = 0; j < 16; j++){
                uint64_t b2 = pack2(__ldg(bias + c0 + 2*j), __ldg(bias + c0 + 2*j + 1));
                accA[j] = b2; accB[j] = b2;
            }
        } else {
            #pragma unroll
            for (int j = 0; j < 16; j++){ accA[j] = 0ull; accB[j] = 0ull; }
        }

        const float* wbase = Wb + c*32;
        #pragma unroll 2
        for (int d = 0; d < 64; d++){
            float2 xv = *(const float2*)(Xs + d*256 + 2*m);
            uint64_t xa = pack2(xv.x, xv.x);
            uint64_t xb = pack2(xv.y, xv.y);
            const ulonglong2* wr = (const ulonglong2*)(wbase + d*64);
            #pragma unroll
            for (int j = 0; j < 8; j++){
                ulonglong2 w = wr[j];
                fma2(accA[2*j],   xa, w.x);
                fma2(accA[2*j+1], xa, w.y);
                fma2(accB[2*j],   xb, w.x);
                fma2(accB[2*j+1], xb, w.y);
            }
        }

        if (node0 < n){
            ulonglong2* oa = (ulonglong2*)(outArr + (size_t)node0*64 + c*32);
            #pragma unroll
            for (int j = 0; j < 8; j++) oa[j] = make_ulonglong2(accA[2*j], accA[2*j+1]);
            if (node0 + 1 < n){
                ulonglong2* ob = (ulonglong2*)(outArr + (size_t)(node0+1)*64 + c*32);
                #pragma unroll
                for (int j = 0; j < 8; j++) ob[j] = make_ulonglong2(accB[2*j], accB[2*j+1]);
            }
        }

        if (att){
            // partial attention dots over this thread's 32 cols, for both nodes
            float aA = 0.f, bA = 0.f, aB = 0.f, bB = 0.f;
            int c0 = c*32;
            #pragma unroll
            for (int j = 0; j < 16; j++){
                float sA = __ldg(atS + c0 + 2*j), sB = __ldg(atS + c0 + 2*j + 1);
                float dA = __ldg(atD + c0 + 2*j), dB = __ldg(atD + c0 + 2*j + 1);
                float loA = __uint_as_float((unsigned)accA[j]);
                float hiA = __uint_as_float((unsigned)(accA[j] >> 32));
                float loB = __uint_as_float((unsigned)accB[j]);
                float hiB = __uint_as_float((unsigned)(accB[j] >> 32));
                aA = fmaf(loA, sA, aA); aA = fmaf(hiA, sB, aA);
                bA = fmaf(loA, dA, bA); bA = fmaf(hiA, dB, bA);
                aB = fmaf(loB, sA, aB); aB = fmaf(hiB, sB, aB);
                bB = fmaf(loB, dA, bB); bB = fmaf(hiB, dB, bB);
            }
            int u0 = 2*m, u1 = 2*m + 1;
            sdot[(c*256 + u0)*2    ] = aA;
            sdot[(c*256 + u0)*2 + 1] = bA;
            sdot[(c*256 + u1)*2    ] = aB;
            sdot[(c*256 + u1)*2 + 1] = bB;
            __syncthreads();
            if (c == 0){
                if (node0 < n){
                    g_asrc[node0] = sdot[u0*2]     + sdot[(256+u0)*2];
                    g_adst[node0] = sdot[u0*2 + 1] + sdot[(256+u0)*2 + 1];
                }
                if (node0 + 1 < n){
                    g_asrc[node0+1] = sdot[u1*2]     + sdot[(256+u1)*2];
                    g_adst[node0+1] = sdot[u1*2 + 1] + sdot[(256+u1)*2 + 1];
                }
            }
        }
    };

    // 13 tiles, explicitly sequenced (no dynamic descriptor arrays -> no LMEM)
    pref(skW, 64, 0);
    tile(0,  nullptr, 0,  g_xs,                        sfW, 128, 0,  false);
    tile(1,  sfb,     0,  g_fsb,                       sfW, 128, 64, false);
    tile(2,  sfb,     64, g_fsg,                       flW, 64,  0,  false);
    tile(3,  nullptr, 0,  g_xr,                        ffW, 128, 0,  false);
    tile(4,  ffb,     0,  g_beta,                      ffW, 128, 64, false);
    tile(5,  ffb,     64, g_gamma,                     flW + 64*64,    64,  0,  false);
    tile(6,  nullptr, 0,  g_xr    + (size_t)n*64,      ffW + 64*128,   128, 0,  false);
    tile(7,  ffb+128, 0,  g_beta  + (size_t)n*64,      ffW + 64*128,   128, 64, false);
    tile(8,  ffb+128, 64, g_gamma + (size_t)n*64,      flW + 2*64*64,  64,  0,  false);
    tile(9,  nullptr, 0,  g_xr    + (size_t)2*n*64,    ffW + 2*64*128, 128, 0,  false);
    tile(10, ffb+256, 0,  g_beta  + (size_t)2*n*64,    ffW + 2*64*128, 128, 64, false);
    tile(11, ffb+256, 64, g_gamma + (size_t)2*n*64,    gatW,           64,  0,  false);
    tile(12, nullptr, 0,  g_xp,                        nullptr, 0, 0,  true);
}

// ---------------- CSR build over (dst*3 + type) keys ----------------
__global__ void khist(const int* __restrict__ dst, const int* __restrict__ et, int E){
    int i = blockIdx.x*blockDim.x + threadIdx.x;
    if (i < E) atomicAdd(&g_cnt[dst[i]*RR + et[i]], 1);
}

__global__ __launch_bounds__(SCB) void kscanA(int m){
    __shared__ int wsum[32];
    int i = blockIdx.x*SCB + threadIdx.x;
    int lane = threadIdx.x & 31, wid = threadIdx.x >> 5;
    int v = (i < m) ? g_cnt[i] : 0;
    int inc = v;
    #pragma unroll
    for (int o = 1; o < 32; o <<= 1){
        int u = __shfl_up_sync(0xffffffffu, inc, o);
        if (lane >= o) inc += u;
    }
    if (lane == 31) wsum[wid] = inc;
    __syncthreads();
    if (wid == 0){
        int s = wsum[lane];
        int t = s;
        #pragma unroll
        for (int o = 1; o < 32; o <<= 1){
            int u = __shfl_up_sync(0xffffffffu, t, o);
            if (lane >= o) t += u;
        }
        wsum[lane] = t - s;
    }
    __syncthreads();
    int excl = inc - v + wsum[wid];
    if (i < m) g_off[i] = excl;
    if (threadIdx.x == SCB-1) g_bsum[blockIdx.x] = excl + v;
}

__global__ void kscanB(int nb){
    __shared__ int ss[256];
    int t = threadIdx.x;
    int v = (t < nb) ? g_bsum[t] : 0;
    ss[t] = v; __syncthreads();
    #pragma unroll
    for (int o = 1; o < 256; o <<= 1){
        int u = (t >= o) ? ss[t-o] : 0;
        __syncthreads();
        ss[t] += u;
        __syncthreads();
    }
    if (t < nb) g_bofs[t] = ss[t] - v;
}

__global__ __launch_bounds__(SCB) void kscanC(int m, int E){
    int i = blockIdx.x*SCB + threadIdx.x;
    if (i < m) g_off[i] += g_bofs[blockIdx.x];
    if (blockIdx.x == 0 && threadIdx.x == 0) g_off[m] = E;
}

__global__ void kscatter(const int* __restrict__ src, const int* __restrict__ dst,
                         const int* __restrict__ et, int E){
    int i = blockIdx.x*blockDim.x + threadIdx.x;
    if (i >= E) return;
    int key = dst[i]*RR + et[i];
    int p = g_off[key] + atomicAdd(&g_pos[key], 1);
    g_rec[p] = src[i];
}

// ---------------- fused edge gather: FiLM + GAT, warp per dst ----------------
__global__ void kedge(const float* __restrict__ gatb, int n){
    int w = (blockIdx.x*blockDim.x + threadIdx.x) >> 5;
    int lane = threadIdx.x & 31;
    if (w >= n) return;

    float aD = g_adst[w];
    float es0 = g_asrc[w] + aD;
    float ssum = __expf(fmaxf(es0, 0.2f*es0));
    float2 xpw = ((const float2*)(g_xp + (size_t)w*64))[lane];
    float2 gacc = make_float2(ssum*xpw.x, ssum*xpw.y);

    float aggx = 0.f, aggy = 0.f;
    int base = w*RR;
    #pragma unroll
    for (int t = 0; t < RR; t++){
        int beg = g_off[base+t], end = g_off[base+t+1];
        if (beg == end) continue;
        const float* xrb = g_xr + (size_t)t*n*64;
        float2 gm = ((const float2*)(g_gamma + ((size_t)t*n + w)*64))[lane];
        float2 bt = ((const float2*)(g_beta  + ((size_t)t*n + w)*64))[lane];
        float ax = 0.f, ay = 0.f;
        int s = g_rec[beg];
        for (int e = beg; e < end; e++){
            int sn = (e+1 < end) ? g_rec[e+1] : 0;
            float2 xv = ((const float2*)(xrb  + (size_t)s*64))[lane];
            float2 pv = ((const float2*)(g_xp + (size_t)s*64))[lane];
            float as = g_asrc[s];
            ax += fmaxf(fmaf(gm.x, xv.x, bt.x), 0.f);
            ay += fmaxf(fmaf(gm.y, xv.y, bt.y), 0.f);
            float es = as + aD;
            float al = __expf(fmaxf(es, 0.2f*es));
            gacc.x = fmaf(al, pv.x, gacc.x);
            gacc.y = fmaf(al, pv.y, gacc.y);
            ssum += al;
            s = sn;
        }
        float inv = 1.f / (float)(end - beg);
        aggx = fmaf(ax, inv, aggx);
        aggy = fmaf(ay, inv, aggy);
    }

    size_t o = (size_t)w*64 + lane*2;
    float2 xs = *(const float2*)(g_xs  + o);
    float2 fb = *(const float2*)(g_fsb + o);
    float2 fg = *(const float2*)(g_fsg + o);
    float o1x = fmaxf(fmaxf(fmaf(fg.x, xs.x, fb.x), 0.f) + aggx, 0.f);
    float o1y = fmaxf(fmaxf(fmaf(fg.y, xs.y, fb.y), 0.f) + aggy, 0.f);
    *(float2*)(g_feats + (size_t)w*128 + 2*lane) = make_float2(o1x, o1y);

    float inv = 1.f / ssum;
    float o2x = fmaxf(fmaf(gacc.x, inv, gatb[2*lane  ]), 0.f);
    float o2y = fmaxf(fmaf(gacc.y, inv, gatb[2*lane+1]), 0.f);
    *(float2*)(g_feats + (size_t)w*128 + 64 + 2*lane) = make_float2(o2x, o2y);
}

// ---------------- pooling: (graph, chunk) partials, then reduce ----------------
__global__ void kpool(const int* __restrict__ gb, int n){
    int g = blockIdx.x / PCH, ch = blockIdx.x % PCH;
    int c = threadIdx.x;
    int lo = 0, hi = n;
    while (lo < hi){ int m = (lo+hi)>>1; if (gb[m] < g) lo = m+1; else hi = m; }
    int start = lo; hi = n;
    while (lo < hi){ int m = (lo+hi)>>1; if (gb[m] < g+1) lo = m+1; else hi = m; }
    int end = lo;
    int len = end - start;
    int b = start + (len*ch)/PCH;
    int e = start + (len*(ch+1))/PCH;
    float mx = 0.f, sm = 0.f;
    for (int i = b; i < e; i++){
        float v = g_feats[(size_t)i*128 + c];
        mx = fmaxf(mx, v); sm += v;
    }
    g_ppmax[(g*PCH + ch)*128 + c] = mx;
    g_ppsum[(g*PCH + ch)*128 + c] = sm;
}

__global__ void kpoolred(const int* __restrict__ gb, int n){
    int g = blockIdx.x, c = threadIdx.x;
    int lo = 0, hi = n;
    while (lo < hi){ int m = (lo+hi)>>1; if (gb[m] < g) lo = m+1; else hi = m; }
    int start = lo; hi = n;
    while (lo < hi){ int m = (lo+hi)>>1; if (gb[m] < g+1) lo = m+1; else hi = m; }
    int cnt = lo - start;
    float mx = 0.f, sm = 0.f;
    #pragma unroll
    for (int ch = 0; ch < PCH; ch++){
        mx = fmaxf(mx, g_ppmax[(g*PCH + ch)*128 + c]);
        sm += g_ppsum[(g*PCH + ch)*128 + c];
    }
    g_pmax[g*128 + c]  = mx;
    g_pmean[g*128 + c] = sm / (float)(cnt > 0 ? cnt : 1);
}

// ---------------- MLP hidden ----------------
__global__ void k6a(const float* __restrict__ linW, const float* __restrict__ linb){
    int idx = blockIdx.x*blockDim.x + threadIdx.x;
    if (idx >= GGR*64) return;
    int g = idx >> 6, j = idx & 63;
    float s = linb[j];
    #pragma unroll 4
    for (int k = 0; k < 128; k++) s = fmaf(g_pmax[g*128 + k],  linW[k*64 + j], s);
    #pragma unroll 4
    for (int k = 0; k < 128; k++) s = fmaf(g_pmean[g*128 + k], linW[(128+k)*64 + j], s);
    g_hidden[idx] = fmaxf(s, 0.f);
}

// ---------------- logits + log_softmax ----------------
__global__ void k6b(const float* __restrict__ fcW, const float* __restrict__ fcb,
                    float* __restrict__ out){
    int g = threadIdx.x;
    if (g >= GGR) return;
    float l[10];
    #pragma unroll
    for (int c = 0; c < 10; c++) l[c] = fcb[c];
    for (int j = 0; j < 64; j++){
        float h = g_hidden[g*64 + j];
        #pragma unroll
        for (int c = 0; c < 10; c++) l[c] = fmaf(h, fcW[j*10 + c], l[c]);
    }
    float mx = l[0];
    #pragma unroll
    for (int c = 1; c < 10; c++) mx = fmaxf(mx, l[c]);
    float se = 0.f;
    #pragma unroll
    for (int c = 0; c < 10; c++) se += expf(l[c] - mx);
    float lse = mx + logf(se);
    #pragma unroll
    for (int c = 0; c < 10; c++) out[g*10 + c] = l[c] - lse;
}

// ---------------- launch ----------------
extern "C" void kernel_launch(void* const* d_in, const int* in_sizes, int n_in,
                              void* d_out, int out_size){
    const float* x    = (const float*)d_in[0];
    const int*   ei   = (const int*)  d_in[1];
    const int*   et   = (const int*)  d_in[2];
    const int*   gb   = (const int*)  d_in[3];
    const float* flW  = (const float*)d_in[4];
    const float* ffW  = (const float*)d_in[5];
    const float* ffb  = (const float*)d_in[6];
    const float* skW  = (const float*)d_in[7];
    const float* sfW  = (const float*)d_in[8];
    const float* sfb  = (const float*)d_in[9];
    const float* gatW = (const float*)d_in[10];
    const float* atS  = (const float*)d_in[11];
    const float* atD  = (const float*)d_in[12];
    const float* gatb = (const float*)d_in[13];
    const float* linW = (const float*)d_in[14];
    const float* linb = (const float*)d_in[15];
    const float* fcW  = (const float*)d_in[16];
    const float* fcb  = (const float*)d_in[17];

    int n = in_sizes[0] / 64;
    int E = in_sizes[1] / 2;
    const int* src = ei;
    const int* dst = ei + E;
    int m = n * RR;

    static cudaStream_t s2 = nullptr;
    static cudaEvent_t evFork = nullptr, evJoin = nullptr;
    if (!s2){
        cudaStreamCreateWithFlags(&s2, cudaStreamNonBlocking);
        cudaEventCreateWithFlags(&evFork, cudaEventDisableTiming);
        cudaEventCreateWithFlags(&evJoin, cudaEventDisableTiming);
        cudaFuncSetAttribute(k1, cudaFuncAttributeMaxDynamicSharedMemorySize, 102400);
    }

    int nbScan = (m + SCB-1)/SCB;
    int smemK1 = 25600 * 4;  // Xs 16384 + W 2*4096 + sdot 1024 floats

    // fork: CSR build on side stream, dense GEMMs on main stream
    cudaEventRecord(evFork, 0);
    cudaStreamWaitEvent(s2, evFork, 0);

    kzero   <<<(m + 255)/256, 256, 0, s2>>>(m);
    khist   <<<(E + 255)/256, 256, 0, s2>>>(dst, et, E);
    kscanA  <<<nbScan, SCB, 0, s2>>>(m);

    k1<<<(n + 255)/256, 256, smemK1>>>(x, flW, ffW, ffb, skW, sfW, sfb, gatW, atS, atD, n);

    kscanB  <<<1, 256, 0, s2>>>(nbScan);
    kscanC  <<<nbScan, SCB, 0, s2>>>(m, E);
    kscatter<<<(E + 255)/256, 256, 0, s2>>>(src, dst, et, E);
    cudaEventRecord(evJoin, s2);

    cudaStreamWaitEvent(0, evJoin, 0);
    kedge<<<(n + 7)/8, 256>>>(gatb, n);
    kpool<<<GGR*PCH, 128>>>(gb, n);
    kpoolred<<<GGR, 128>>>(gb, n);
    k6a<<<(GGR*64 + 127)/128, 128>>>(linW, linb);
    k6b<<<1, 64>>>(fcW, fcb, (float*)d_out);
}

// round 17
// speedup vs baseline: 1.6732x; 1.1313x over previous
#include <cuda_runtime.h>
#include <cstdint>

#define NMAX 50000
#define EMAX 800000
#define RR 3
#define GGR 64
#define PCH 8
#define SCB 1024

// ---------------- scratch (device globals; no allocation) ----------------
__device__ float g_xr   [RR*NMAX*64];
__device__ float g_beta [RR*NMAX*64];
__device__ float g_gamma[RR*NMAX*64];
__device__ float g_xs   [NMAX*64];
__device__ float g_fsb  [NMAX*64];
__device__ float g_fsg  [NMAX*64];
__device__ float g_xp   [NMAX*64];
__device__ float g_asrc [NMAX];
__device__ float g_adst [NMAX];
__device__ int      g_cnt[RR*NMAX];
__device__ int      g_pos[RR*NMAX];
__device__ int      g_off[RR*NMAX+1];
__device__ int      g_bsum[256];
__device__ int      g_bofs[256];
__device__ int      g_rec[EMAX];
__device__ float g_feats[NMAX*128];
__device__ float g_ppmax[GGR*PCH*128];
__device__ float g_ppsum[GGR*PCH*128];
__device__ float g_pmax [GGR*128];
__device__ float g_pmean[GGR*128];
__device__ float g_hidden[GGR*64];

// ---------------- helpers ----------------
__device__ __forceinline__ uint64_t pack2(float a, float b){
    uint64_t r; asm("mov.b64 %0,{%1,%2};" : "=l"(r) : "f"(a), "f"(b)); return r;
}
__device__ __forceinline__ void fma2(uint64_t &d, uint64_t a, uint64_t b){
    asm("fma.rn.f32x2 %0,%1,%2,%0;" : "+l"(d) : "l"(a), "l"(b));
}
__device__ __forceinline__ void cpasync16(uint32_t dst, const void* src){
    asm volatile("cp.async.ca.shared.global [%0], [%1], 16;" :: "r"(dst), "l"(src));
}
#define CP_COMMIT() asm volatile("cp.async.commit_group;")
#define CP_WAIT0()  asm volatile("cp.async.wait_group 0;" ::: "memory")

// ---------------- init: zero CSR counters ----------------
__global__ void kzero(int m){
    int i = blockIdx.x*blockDim.x + threadIdx.x;
    if (i < m){ g_cnt[i] = 0; g_pos[i] = 0; }
}

// ---------------- K1 tile compute: one shared SASS copy (I$-friendly) ------
// thread (c = tid>>5 in 0..3, mm = tid&31): nodes {node0, node0+1}, cols [16c,16c+16)
__device__ __noinline__ void k1_tile(
    const float* __restrict__ Wb, const float* __restrict__ Xs,
    float* __restrict__ sdot,
    const float* __restrict__ bias, int bof, float* __restrict__ outArr,
    int c, int mm, int node0, int n,
    const float* __restrict__ atS, const float* __restrict__ atD, int att)
{
    uint64_t accA[8], accB[8];
    if (bias){
        int c0 = bof + c*16;
        #pragma unroll
        for (int j = 0; j < 8; j++){
            uint64_t b2 = pack2(__ldg(bias + c0 + 2*j), __ldg(bias + c0 + 2*j + 1));
            accA[j] = b2; accB[j] = b2;
        }
    } else {
        #pragma unroll
        for (int j = 0; j < 8; j++){ accA[j] = 0ull; accB[j] = 0ull; }
    }

    const float* wp = Wb + c*16;
    const float* xp = Xs + 2*mm;
    #pragma unroll 2
    for (int d = 0; d < 64; d++){
        float2 xv = *(const float2*)xp;
        uint64_t xa = pack2(xv.x, xv.x);
        uint64_t xb = pack2(xv.y, xv.y);
        const ulonglong2* wr = (const ulonglong2*)wp;
        #pragma unroll
        for (int j = 0; j < 4; j++){
            ulonglong2 w = wr[j];
            fma2(accA[2*j],   xa, w.x);
            fma2(accA[2*j+1], xa, w.y);
            fma2(accB[2*j],   xb, w.x);
            fma2(accB[2*j+1], xb, w.y);
        }
        wp += 64; xp += 64;
    }

    if (node0 < n){
        ulonglong2* oa = (ulonglong2*)(outArr + (size_t)node0*64 + c*16);
        #pragma unroll
        for (int j = 0; j < 4; j++) oa[j] = make_ulonglong2(accA[2*j], accA[2*j+1]);
        if (node0 + 1 < n){
            ulonglong2* ob = (ulonglong2*)(outArr + (size_t)(node0+1)*64 + c*16);
            #pragma unroll
            for (int j = 0; j < 4; j++) ob[j] = make_ulonglong2(accB[2*j], accB[2*j+1]);
        }
    }

    if (att){
        float aA = 0.f, bA = 0.f, aB = 0.f, bB = 0.f;
        int c0 = c*16;
        #pragma unroll
        for (int j = 0; j < 8; j++){
            float s0 = __ldg(atS + c0 + 2*j), s1 = __ldg(atS + c0 + 2*j + 1);
            float d0 = __ldg(atD + c0 + 2*j), d1 = __ldg(atD + c0 + 2*j + 1);
            float loA = __uint_as_float((unsigned)accA[j]);
            float hiA = __uint_as_float((unsigned)(accA[j] >> 32));
            float loB = __uint_as_float((unsigned)accB[j]);
            float hiB = __uint_as_float((unsigned)(accB[j] >> 32));
            aA = fmaf(loA, s0, aA); aA = fmaf(hiA, s1, aA);
            bA = fmaf(loA, d0, bA); bA = fmaf(hiA, d1, bA);
            aB = fmaf(loB, s0, aB); aB = fmaf(hiB, s1, aB);
            bB = fmaf(loB, d0, bB); bB = fmaf(hiB, d1, bB);
        }
        int u0 = 2*mm, u1 = 2*mm + 1;
        sdot[(c*64 + u0)*2    ] = aA;
        sdot[(c*64 + u0)*2 + 1] = bA;
        sdot[(c*64 + u1)*2    ] = aB;
        sdot[(c*64 + u1)*2 + 1] = bB;
        __syncthreads();
        if (c == 0){
            if (node0 < n){
                float sa = 0.f, sb = 0.f;
                #pragma unroll
                for (int g = 0; g < 4; g++){ sa += sdot[(g*64+u0)*2]; sb += sdot[(g*64+u0)*2+1]; }
                g_asrc[node0] = sa; g_adst[node0] = sb;
            }
            if (node0 + 1 < n){
                float sa = 0.f, sb = 0.f;
                #pragma unroll
                for (int g = 0; g < 4; g++){ sa += sdot[(g*64+u1)*2]; sb += sdot[(g*64+u1)*2+1]; }
                g_asrc[node0+1] = sa; g_adst[node0+1] = sb;
            }
        }
    }
}

// ---------------- K1: fused node-dense GEMMs, cp.async double-buffered -----
__global__ __launch_bounds__(128) void k1(
    const float* __restrict__ x,
    const float* __restrict__ flW, const float* __restrict__ ffW, const float* __restrict__ ffb,
    const float* __restrict__ skW, const float* __restrict__ sfW, const float* __restrict__ sfb,
    const float* __restrict__ gatW,
    const float* __restrict__ atS, const float* __restrict__ atD, int n)
{
    extern __shared__ float sm[];
    float* Xs   = sm;            // 64*64 = 4096 floats
    float* Wbuf = sm + 4096;     // 2*4096 floats
    float* sdot = sm + 12288;    // 512 floats

    int tid = threadIdx.x;
    int c   = tid >> 5;
    int mm  = tid & 31;
    int nbase = blockIdx.x*64;
    int node0 = nbase + 2*mm;

    uint32_t wsm0 = (uint32_t)__cvta_generic_to_shared(Wbuf);

    // issue weights for tile into buffer (32 floats per thread, 8x cp.async 16B)
    auto issueW = [&](const float* Wg, int ldw, int jof, int buf){
        uint32_t base = wsm0 + buf*16384;
        #pragma unroll
        for (int q = 0; q < 8; q++){
            int k = tid*32 + q*4;
            cpasync16(base + k*4, Wg + (size_t)(k>>6)*ldw + jof + (k&63));
        }
        CP_COMMIT();
    };

    issueW(skW, 64, 0, 0);   // prologue: tile 0 into buf0

    // stage x transposed: thread (nl = tid&63, hf = tid>>6) loads 32 floats
    {
        int nl = tid & 63, hf = tid >> 6;
        int nd = nbase + nl;
        int nc = nd < n ? nd : n-1;
        const float4* xp4 = (const float4*)(x + (size_t)nc*64) + hf*8;
        #pragma unroll
        for (int q = 0; q < 8; q++){
            float4 v = xp4[q];
            int d = hf*32 + 4*q;
            Xs[(d+0)*64 + nl] = v.x;
            Xs[(d+1)*64 + nl] = v.y;
            Xs[(d+2)*64 + nl] = v.z;
            Xs[(d+3)*64 + nl] = v.w;
        }
    }

    float* B0 = Wbuf;
    float* B1 = Wbuf + 4096;

    // t: wait W[t]; sync; issue W[t+1] (opposite buffer); compute t
    CP_WAIT0(); __syncthreads();
    issueW(sfW, 128, 0, 1);
    k1_tile(B0, Xs, sdot, nullptr, 0, g_xs, c, mm, node0, n, atS, atD, 0);

    CP_WAIT0(); __syncthreads();
    issueW(sfW, 128, 64, 0);
    k1_tile(B1, Xs, sdot, sfb, 0, g_fsb, c, mm, node0, n, atS, atD, 0);

    CP_WAIT0(); __syncthreads();
    issueW(flW, 64, 0, 1);
    k1_tile(B0, Xs, sdot, sfb, 64, g_fsg, c, mm, node0, n, atS, atD, 0);

    CP_WAIT0(); __syncthreads();
    issueW(ffW, 128, 0, 0);
    k1_tile(B1, Xs, sdot, nullptr, 0, g_xr, c, mm, node0, n, atS, atD, 0);

    CP_WAIT0(); __syncthreads();
    issueW(ffW, 128, 64, 1);
    k1_tile(B0, Xs, sdot, ffb, 0, g_beta, c, mm, node0, n, atS, atD, 0);

    CP_WAIT0(); __syncthreads();
    issueW(flW + 64*64, 64, 0, 0);
    k1_tile(B1, Xs, sdot, ffb, 64, g_gamma, c, mm, node0, n, atS, atD, 0);

    CP_WAIT0(); __syncthreads();
    issueW(ffW + 64*128, 128, 0, 1);
    k1_tile(B0, Xs, sdot, nullptr, 0, g_xr + (size_t)n*64, c, mm, node0, n, atS, atD, 0);

    CP_WAIT0(); __syncthreads();
    issueW(ffW + 64*128, 128, 64, 0);
    k1_tile(B1, Xs, sdot, ffb+128, 0, g_beta + (size_t)n*64, c, mm, node0, n, atS, atD, 0);

    CP_WAIT0(); __syncthreads();
    issueW(flW + 2*64*64, 64, 0, 1);
    k1_tile(B0, Xs, sdot, ffb+128, 64, g_gamma + (size_t)n*64, c, mm, node0, n, atS, atD, 0);

    CP_WAIT0(); __syncthreads();
    issueW(ffW + 2*64*128, 128, 0, 0);
    k1_tile(B1, Xs, sdot, nullptr, 0, g_xr + (size_t)2*n*64, c, mm, node0, n, atS, atD, 0);

    CP_WAIT0(); __syncthreads();
    issueW(ffW + 2*64*128, 128, 64, 1);
    k1_tile(B0, Xs, sdot, ffb+256, 0, g_beta + (size_t)2*n*64, c, mm, node0, n, atS, atD, 0);

    CP_WAIT0(); __syncthreads();
    issueW(gatW, 64, 0, 0);
    k1_tile(B1, Xs, sdot, ffb+256, 64, g_gamma + (size_t)2*n*64, c, mm, node0, n, atS, atD, 0);

    CP_WAIT0(); __syncthreads();
    k1_tile(B0, Xs, sdot, nullptr, 0, g_xp, c, mm, node0, n, atS, atD, 1);
}

// ---------------- CSR build over (dst*3 + type) keys ----------------
__global__ void khist(const int* __restrict__ dst, const int* __restrict__ et, int E){
    int i = blockIdx.x*blockDim.x + threadIdx.x;
    if (i < E) atomicAdd(&g_cnt[dst[i]*RR + et[i]], 1);
}

__global__ __launch_bounds__(SCB) void kscanA(int m){
    __shared__ int wsum[32];
    int i = blockIdx.x*SCB + threadIdx.x;
    int lane = threadIdx.x & 31, wid = threadIdx.x >> 5;
    int v = (i < m) ? g_cnt[i] : 0;
    int inc = v;
    #pragma unroll
    for (int o = 1; o < 32; o <<= 1){
        int u = __shfl_up_sync(0xffffffffu, inc, o);
        if (lane >= o) inc += u;
    }
    if (lane == 31) wsum[wid] = inc;
    __syncthreads();
    if (wid == 0){
        int s = wsum[lane];
        int t = s;
        #pragma unroll
        for (int o = 1; o < 32; o <<= 1){
            int u = __shfl_up_sync(0xffffffffu, t, o);
            if (lane >= o) t += u;
        }
        wsum[lane] = t - s;
    }
    __syncthreads();
    int excl = inc - v + wsum[wid];
    if (i < m) g_off[i] = excl;
    if (threadIdx.x == SCB-1) g_bsum[blockIdx.x] = excl + v;
}

__global__ void kscanB(int nb){
    __shared__ int ss[256];
    int t = threadIdx.x;
    int v = (t < nb) ? g_bsum[t] : 0;
    ss[t] = v; __syncthreads();
    #pragma unroll
    for (int o = 1; o < 256; o <<= 1){
        int u = (t >= o) ? ss[t-o] : 0;
        __syncthreads();
        ss[t] += u;
        __syncthreads();
    }
    if (t < nb) g_bofs[t] = ss[t] - v;
}

__global__ __launch_bounds__(SCB) void kscanC(int m, int E){
    int i = blockIdx.x*SCB + threadIdx.x;
    if (i < m) g_off[i] += g_bofs[blockIdx.x];
    if (blockIdx.x == 0 && threadIdx.x == 0) g_off[m] = E;
}

__global__ void kscatter(const int* __restrict__ src, const int* __restrict__ dst,
                         const int* __restrict__ et, int E){
    int i = blockIdx.x*blockDim.x + threadIdx.x;
    if (i >= E) return;
    int key = dst[i]*RR + et[i];
    int p = g_off[key] + atomicAdd(&g_pos[key], 1);
    g_rec[p] = src[i];
}

// ---------------- fused edge gather: FiLM + GAT, warp per dst ----------------
__global__ void kedge(const float* __restrict__ gatb, int n){
    int w = (blockIdx.x*blockDim.x + threadIdx.x) >> 5;
    int lane = threadIdx.x & 31;
    if (w >= n) return;

    float aD = g_adst[w];
    float es0 = g_asrc[w] + aD;
    float ssum = __expf(fmaxf(es0, 0.2f*es0));
    float2 xpw = ((const float2*)(g_xp + (size_t)w*64))[lane];
    float2 gacc = make_float2(ssum*xpw.x, ssum*xpw.y);

    float aggx = 0.f, aggy = 0.f;
    int base = w*RR;
    #pragma unroll
    for (int t = 0; t < RR; t++){
        int beg = g_off[base+t], end = g_off[base+t+1];
        if (beg == end) continue;
        const float* xrb = g_xr + (size_t)t*n*64;
        float2 gm = ((const float2*)(g_gamma + ((size_t)t*n + w)*64))[lane];
        float2 bt = ((const float2*)(g_beta  + ((size_t)t*n + w)*64))[lane];
        float ax = 0.f, ay = 0.f;
        int s = g_rec[beg];
        for (int e = beg; e < end; e++){
            int sn = (e+1 < end) ? g_rec[e+1] : 0;
            float2 xv = ((const float2*)(xrb  + (size_t)s*64))[lane];
            float2 pv = ((const float2*)(g_xp + (size_t)s*64))[lane];
            float as = g_asrc[s];
            ax += fmaxf(fmaf(gm.x, xv.x, bt.x), 0.f);
            ay += fmaxf(fmaf(gm.y, xv.y, bt.y), 0.f);
            float es = as + aD;
            float al = __expf(fmaxf(es, 0.2f*es));
            gacc.x = fmaf(al, pv.x, gacc.x);
            gacc.y = fmaf(al, pv.y, gacc.y);
            ssum += al;
            s = sn;
        }
        float inv = 1.f / (float)(end - beg);
        aggx = fmaf(ax, inv, aggx);
        aggy = fmaf(ay, inv, aggy);
    }

    size_t o = (size_t)w*64 + lane*2;
    float2 xs = *(const float2*)(g_xs  + o);
    float2 fb = *(const float2*)(g_fsb + o);
    float2 fg = *(const float2*)(g_fsg + o);
    float o1x = fmaxf(fmaxf(fmaf(fg.x, xs.x, fb.x), 0.f) + aggx, 0.f);
    float o1y = fmaxf(fmaxf(fmaf(fg.y, xs.y, fb.y), 0.f) + aggy, 0.f);
    *(float2*)(g_feats + (size_t)w*128 + 2*lane) = make_float2(o1x, o1y);

    float inv = 1.f / ssum;
    float o2x = fmaxf(fmaf(gacc.x, inv, gatb[2*lane  ]), 0.f);
    float o2y = fmaxf(fmaf(gacc.y, inv, gatb[2*lane+1]), 0.f);
    *(float2*)(g_feats + (size_t)w*128 + 64 + 2*lane) = make_float2(o2x, o2y);
}

// ---------------- pooling: (graph, chunk) partials, then reduce ----------------
__global__ void kpool(const int* __restrict__ gb, int n){
    int g = blockIdx.x / PCH, ch = blockIdx.x % PCH;
    int c = threadIdx.x;
    int lo = 0, hi = n;
    while (lo < hi){ int m = (lo+hi)>>1; if (gb[m] < g) lo = m+1; else hi = m; }
    int start = lo; hi = n;
    while (lo < hi){ int m = (lo+hi)>>1; if (gb[m] < g+1) lo = m+1; else hi = m; }
    int end = lo;
    int len = end - start;
    int b = start + (len*ch)/PCH;
    int e = start + (len*(ch+1))/PCH;
    float mx = 0.f, sm = 0.f;
    for (int i = b; i < e; i++){
        float v = g_feats[(size_t)i*128 + c];
        mx = fmaxf(mx, v); sm += v;
    }
    g_ppmax[(g*PCH + ch)*128 + c] = mx;
    g_ppsum[(g*PCH + ch)*128 + c] = sm;
}

__global__ void kpoolred(const int* __restrict__ gb, int n){
    int g = blockIdx.x, c = threadIdx.x;
    int lo = 0, hi = n;
    while (lo < hi){ int m = (lo+hi)>>1; if (gb[m] < g) lo = m+1; else hi = m; }
    int start = lo; hi = n;
    while (lo < hi){ int m = (lo+hi)>>1; if (gb[m] < g+1) lo = m+1; else hi = m; }
    int cnt = lo - start;
    float mx = 0.f, sm = 0.f;
    #pragma unroll
    for (int ch = 0; ch < PCH; ch++){
        mx = fmaxf(mx, g_ppmax[(g*PCH + ch)*128 + c]);
        sm += g_ppsum[(g*PCH + ch)*128 + c];
    }
    g_pmax[g*128 + c]  = mx;
    g_pmean[g*128 + c] = sm / (float)(cnt > 0 ? cnt : 1);
}

// ---------------- MLP hidden ----------------
__global__ void k6a(const float* __restrict__ linW, const float* __restrict__ linb){
    int idx = blockIdx.x*blockDim.x + threadIdx.x;
    if (idx >= GGR*64) return;
    int g = idx >> 6, j = idx & 63;
    float s = linb[j];
    #pragma unroll 4
    for (int k = 0; k < 128; k++) s = fmaf(g_pmax[g*128 + k],  linW[k*64 + j], s);
    #pragma unroll 4
    for (int k = 0; k < 128; k++) s = fmaf(g_pmean[g*128 + k], linW[(128+k)*64 + j], s);
    g_hidden[idx] = fmaxf(s, 0.f);
}

// ---------------- logits + log_softmax ----------------
__global__ void k6b(const float* __restrict__ fcW, const float* __restrict__ fcb,
                    float* __restrict__ out){
    int g = threadIdx.x;
    if (g >= GGR) return;
    float l[10];
    #pragma unroll
    for (int c = 0; c < 10; c++) l[c] = fcb[c];
    for (int j = 0; j < 64; j++){
        float h = g_hidden[g*64 + j];
        #pragma unroll
        for (int c = 0; c < 10; c++) l[c] = fmaf(h, fcW[j*10 + c], l[c]);
    }
    float mx = l[0];
    #pragma unroll
    for (int c = 1; c < 10; c++) mx = fmaxf(mx, l[c]);
    float se = 0.f;
    #pragma unroll
    for (int c = 0; c < 10; c++) se += expf(l[c] - mx);
    float lse = mx + logf(se);
    #pragma unroll
    for (int c = 0; c < 10; c++) out[g*10 + c] = l[c] - lse;
}

// ---------------- launch ----------------
extern "C" void kernel_launch(void* const* d_in, const int* in_sizes, int n_in,
                              void* d_out, int out_size){
    const float* x    = (const float*)d_in[0];
    const int*   ei   = (const int*)  d_in[1];
    const int*   et   = (const int*)  d_in[2];
    const int*   gb   = (const int*)  d_in[3];
    const float* flW  = (const float*)d_in[4];
    const float* ffW  = (const float*)d_in[5];
    const float* ffb  = (const float*)d_in[6];
    const float* skW  = (const float*)d_in[7];
    const float* sfW  = (const float*)d_in[8];
    const float* sfb  = (const float*)d_in[9];
    const float* gatW = (const float*)d_in[10];
    const float* atS  = (const float*)d_in[11];
    const float* atD  = (const float*)d_in[12];
    const float* gatb = (const float*)d_in[13];
    const float* linW = (const float*)d_in[14];
    const float* linb = (const float*)d_in[15];
    const float* fcW  = (const float*)d_in[16];
    const float* fcb  = (const float*)d_in[17];

    int n = in_sizes[0] / 64;
    int E = in_sizes[1] / 2;
    const int* src = ei;
    const int* dst = ei + E;
    int m = n * RR;

    static cudaStream_t s2 = nullptr;
    static cudaEvent_t evFork = nullptr, evJoin = nullptr;
    if (!s2){
        cudaStreamCreateWithFlags(&s2, cudaStreamNonBlocking);
        cudaEventCreateWithFlags(&evFork, cudaEventDisableTiming);
        cudaEventCreateWithFlags(&evJoin, cudaEventDisableTiming);
        cudaFuncSetAttribute(k1, cudaFuncAttributeMaxDynamicSharedMemorySize, 65536);
    }

    int nbScan = (m + SCB-1)/SCB;
    int smemK1 = 12800 * 4;  // Xs 4096 + W 2*4096 + sdot 512 floats = 50KB

    // fork: CSR build on side stream, dense GEMMs on main stream
    cudaEventRecord(evFork, 0);
    cudaStreamWaitEvent(s2, evFork, 0);

    kzero   <<<(m + 255)/256, 256, 0, s2>>>(m);
    khist   <<<(E + 255)/256, 256, 0, s2>>>(dst, et, E);
    kscanA  <<<nbScan, SCB, 0, s2>>>(m);

    k1<<<(n + 63)/64, 128, smemK1>>>(x, flW, ffW, ffb, skW, sfW, sfb, gatW, atS, atD, n);

    kscanB  <<<1, 256, 0, s2>>>(nbScan);
    kscanC  <<<nbScan, SCB, 0, s2>>>(m, E);
    kscatter<<<(E + 255)/256, 256, 0, s2>>>(src, dst, et, E);
    cudaEventRecord(evJoin, s2);

    cudaStreamWaitEvent(0, evJoin, 0);
    kedge<<<(n + 7)/8, 256>>>(gatb, n);
    kpool<<<GGR*PCH, 128>>>(gb, n);
    kpoolred<<<GGR, 128>>>(gb, n);
    k6a<<<(GGR*64 + 127)/128, 128>>>(linW, linb);
    k6b<<<1, 64>>>(fcW, fcb, (float*)d_out);
}